// round 11
// baseline (speedup 1.0000x reference)
#include <cuda_runtime.h>
#include <cuda_bf16.h>

#define BB 512
#define LL 2048
#define CC 64
#define START_S 62
#define STOP_S 63
#define MID 1023

// scratch (no cudaMalloc allowed)
__device__ unsigned g_eTbfF[CC * 32]; // fwd:  [cp][k2] = bf16x2{exp(T[2k2][cp]), exp(T[2k2+1][cp])}
__device__ unsigned g_eTbfB[CC * 32]; // bwd:  [c][k2]  = bf16x2{exp(T[c][2k2]),  exp(T[c][2k2+1])}
__device__ float g_eTstop[CC];        // exp(T[c][STOP])
__device__ float g_trow_start[CC];    // T[START][c]
__device__ float g_part[BB];
__device__ float g_scores[BB];

// bf16x2 packed ops
__device__ __forceinline__ unsigned bffma(unsigned a, unsigned b, unsigned c) {
    unsigned d;
    asm("fma.rn.bf16x2 %0, %1, %2, %3;" : "=r"(d) : "r"(a), "r"(b), "r"(c));
    return d;
}
__device__ __forceinline__ unsigned bfadd(unsigned a, unsigned b) {
    unsigned d;
    asm("add.rn.bf16x2 %0, %1, %2;" : "=r"(d) : "r"(a), "r"(b));
    return d;
}
__device__ __forceinline__ float bfsum(unsigned ab) {
    float lo = __uint_as_float(ab << 16);
    float hi = __uint_as_float(ab & 0xffff0000u);
    return lo + hi;
}
__device__ __forceinline__ unsigned bfpack(float x, float y) {
    unsigned d;
    asm("cvt.rn.bf16x2.f32 %0, %1, %2;" : "=r"(d) : "f"(y), "f"(x));
    return d;
}

// ---------------------------------------------------------------------------
// Precompute both packed exp(T) tables + boundary vectors.
// ---------------------------------------------------------------------------
__global__ void prep_kernel(const float* __restrict__ T) {
    int i = blockIdx.x * blockDim.x + threadIdx.x;
    if (i < CC * 32) {
        int c  = i >> 5;
        int k2 = i & 31;
        __nv_bfloat162 pf = __floats2bfloat162_rn(__expf(T[(2 * k2) * CC + c]),
                                                  __expf(T[(2 * k2 + 1) * CC + c]));
        g_eTbfF[i] = *reinterpret_cast<unsigned*>(&pf);
        __nv_bfloat162 pb = __floats2bfloat162_rn(__expf(T[c * CC + 2 * k2]),
                                                  __expf(T[c * CC + 2 * k2 + 1]));
        g_eTbfB[i] = *reinterpret_cast<unsigned*>(&pb);
    }
    if (i < CC) {
        g_eTstop[i]     = __expf(T[i * CC + STOP_S]);
        g_trow_start[i] = T[START_S * CC + i];
    }
}

// FOUR interleaved 64-dots: fwd pair + bwd pair (independent chains fill
// each other's latency shadow). 128 HFMA2, 16 accumulators of depth 8.
__device__ __forceinline__ void dot4(const unsigned* __restrict__ vF,
                                     const unsigned* __restrict__ vB,
                                     const unsigned* __restrict__ eFA,
                                     const unsigned* __restrict__ eFB,
                                     const unsigned* __restrict__ eBA,
                                     const unsigned* __restrict__ eBB,
                                     float& rf0, float& rf1,
                                     float& rb0, float& rb1) {
    const uint4* qF = reinterpret_cast<const uint4*>(vF);
    const uint4* qB = reinterpret_cast<const uint4*>(vB);
    unsigned f00 = 0, f01 = 0, f02 = 0, f03 = 0;
    unsigned f10 = 0, f11 = 0, f12 = 0, f13 = 0;
    unsigned b00 = 0, b01 = 0, b02 = 0, b03 = 0;
    unsigned b10 = 0, b11 = 0, b12 = 0, b13 = 0;
#pragma unroll
    for (int j = 0; j < 8; ++j) {
        uint4 x = qF[j];
        uint4 y = qB[j];
        f00 = bffma(x.x, eFA[4 * j + 0], f00);
        b00 = bffma(y.x, eBA[4 * j + 0], b00);
        f10 = bffma(x.x, eFB[4 * j + 0], f10);
        b10 = bffma(y.x, eBB[4 * j + 0], b10);
        f01 = bffma(x.y, eFA[4 * j + 1], f01);
        b01 = bffma(y.y, eBA[4 * j + 1], b01);
        f11 = bffma(x.y, eFB[4 * j + 1], f11);
        b11 = bffma(y.y, eBB[4 * j + 1], b11);
        f02 = bffma(x.z, eFA[4 * j + 2], f02);
        b02 = bffma(y.z, eBA[4 * j + 2], b02);
        f12 = bffma(x.z, eFB[4 * j + 2], f12);
        b12 = bffma(y.z, eBB[4 * j + 2], b12);
        f03 = bffma(x.w, eFA[4 * j + 3], f03);
        b03 = bffma(y.w, eBA[4 * j + 3], b03);
        f13 = bffma(x.w, eFB[4 * j + 3], f13);
        b13 = bffma(y.w, eBB[4 * j + 3], b13);
    }
    rf0 = bfsum(bfadd(bfadd(f00, f01), bfadd(f02, f03)));
    rf1 = bfsum(bfadd(bfadd(f10, f11), bfadd(f12, f13)));
    rb0 = bfsum(bfadd(bfadd(b00, b01), bfadd(b02, b03)));
    rb1 = bfsum(bfadd(bfadd(b10, b11), bfadd(b12, b13)));
}

// bwd-only dot (tail step)
__device__ __forceinline__ void dot2(const unsigned* __restrict__ v,
                                     const unsigned* __restrict__ eA,
                                     const unsigned* __restrict__ eB,
                                     float& ra, float& rb) {
    const uint4* q = reinterpret_cast<const uint4*>(v);
    unsigned a0 = 0, a1 = 0, a2 = 0, a3 = 0;
    unsigned b0 = 0, b1 = 0, b2 = 0, b3 = 0;
#pragma unroll
    for (int j = 0; j < 8; ++j) {
        uint4 x = q[j];
        a0 = bffma(x.x, eA[4 * j + 0], a0);
        b0 = bffma(x.x, eB[4 * j + 0], b0);
        a1 = bffma(x.y, eA[4 * j + 1], a1);
        b1 = bffma(x.y, eB[4 * j + 1], b1);
        a2 = bffma(x.z, eA[4 * j + 2], a2);
        b2 = bffma(x.z, eB[4 * j + 2], b2);
        a3 = bffma(x.w, eA[4 * j + 3], a3);
        b3 = bffma(x.w, eB[4 * j + 3], b3);
    }
    ra = bfsum(bfadd(bfadd(a0, a1), bfadd(a2, a3)));
    rb = bfsum(bfadd(bfadd(b0, b1), bfadd(b2, b3)));
}

// one SUPERSTEP: one forward step (emission ef/mf) + one backward step
// (emission eg/mg), both chains in the same warp. MODE: 0 plain,
// 1 launch warp-maxes, 2 apply renorms.
template <int MODE>
__device__ __forceinline__ void sstep(float2 ef, float mf, float2 eg, float mg,
                                      float& vf0, float& vf1, float& Sf, float& mxF,
                                      float& w0,  float& w1,  float& Sb, float& mxB,
                                      int& cur,
                                      unsigned (*vF)[32], unsigned (*vB)[32],
                                      const unsigned* __restrict__ eFA,
                                      const unsigned* __restrict__ eFB,
                                      const unsigned* __restrict__ eBA,
                                      const unsigned* __restrict__ eBB,
                                      int lane) {
    if (MODE == 1) {            // warp-maxes — overlap the dots
        float x = fmaxf(vf0, vf1);
        float y = fmaxf(w0, w1);
#pragma unroll
        for (int o = 16; o; o >>= 1) {
            x = fmaxf(x, __shfl_xor_sync(0xffffffffu, x, o));
            y = fmaxf(y, __shfl_xor_sync(0xffffffffu, y, o));
        }
        mxF = x; mxB = y;
    }
    float ef0 = __expf(ef.x), ef1 = __expf(ef.y);
    float eg0 = __expf(eg.x), eg1 = __expf(eg.y);
    float vrf0 = vf0, vrf1 = vf1, vrb0 = w0, vrb1 = w1;
    if (MODE == 2) {            // fold r = 1/max into emission factors
        float rF = __fdividef(1.0f, mxF);
        float rB = __fdividef(1.0f, mxB);
        Sf += __logf(mxF);
        Sb += __logf(mxB);
        ef0 *= rF; ef1 *= rF; vrf0 *= rF; vrf1 *= rF;
        eg0 *= rB; eg1 *= rB; vrb0 *= rB; vrb1 *= rB;
    }
    int nxt = cur ^ 1;
    vB[nxt][lane] = bfpack(w0 * eg0, w1 * eg1);   // u = e ⊙ w (renorm folded)
    __syncwarp();                                  // publishes u AND last vF store
    float af0, af1, ab0, ab1;
    dot4(vF[cur], vB[nxt], eFA, eFB, eBA, eBB, af0, af1, ab0, ab1);
    vf0 = (mf > 0.f) ? af0 * ef0 : vrf0;
    vf1 = (mf > 0.f) ? af1 * ef1 : vrf1;
    w0  = (mg > 0.f) ? ab0 : vrb0;
    w1  = (mg > 0.f) ? ab1 : vrb1;
    vF[nxt][lane] = bfpack(vf0, vf1);
    cur = nxt;
}

// ---------------------------------------------------------------------------
// Bidirectional forward algorithm, BOTH directions fused in ONE warp.
// 128 CTAs x 128 threads: 4 batches per CTA, one warp per batch -> 512 warps
// spread exactly one per SMSP (wid%4 covers all 4 schedulers; grid 128 < 148
// SMs). Lane owns states (2*lane, 2*lane+1) of both chains; all 4 exp(T)
// columns/rows live in 128 bf16x2 registers. The two independent chains'
// dots interleave (dot4) to hide each other's LDS/FMA latency; one
// __syncwarp per superstep, no __syncthreads anywhere.
//   logZ = log( sum_c alpha_MID[c] * w_MID[c] ) + S_f + S_b.
// Renorm every 4 supersteps (both chains), max-shuffles pipelined off-chain.
// ---------------------------------------------------------------------------
__global__ void __launch_bounds__(128, 1) alpha_kernel(const float* __restrict__ em,
                                                       const float* __restrict__ mask) {
    const int lane = threadIdx.x & 31;
    const int wid  = threadIdx.x >> 5;
    const int b    = blockIdx.x * 4 + wid;

    __shared__ __align__(16) unsigned shF[4][2][32];
    __shared__ __align__(16) unsigned shB[4][2][32];
    unsigned (*vF)[32] = shF[wid];
    unsigned (*vB)[32] = shB[wid];

    // 4 packed exp(T) columns/rows
    unsigned eFA[32], eFB[32], eBA[32], eBB[32];
    {
        const unsigned* ga = g_eTbfF + (2 * lane) * 32;
        const unsigned* gb = g_eTbfF + (2 * lane + 1) * 32;
        const unsigned* gc = g_eTbfB + (2 * lane) * 32;
        const unsigned* gd = g_eTbfB + (2 * lane + 1) * 32;
#pragma unroll
        for (int k = 0; k < 32; ++k) {
            eFA[k] = ga[k]; eFB[k] = gb[k];
            eBA[k] = gc[k]; eBB[k] = gd[k];
        }
    }

    const float* emb = em + (size_t)b * (LL * CC);
    const float* mkb = mask + (size_t)b * LL;
    const float2* emb2 = reinterpret_cast<const float2*>(emb) + lane;

    // fwd init (t = 0)
    float vf0 = __expf(emb2[0].x + g_trow_start[2 * lane]);
    float vf1 = __expf(emb2[0].y + g_trow_start[2 * lane + 1]);
    float Sf = 0.0f, mxF = 0.0f;
    vF[0][lane] = bfpack(vf0, vf1);

    // bwd init (seed = exp(T[:,STOP]))
    float w0 = g_eTstop[2 * lane];
    float w1 = g_eTstop[2 * lane + 1];
    float Sb = 0.0f, mxB = 0.0f;

    // pipelines, distance 2 each
    float2 fea = emb2[1 * 32],               feb = emb2[2 * 32];
    float  fma_ = mkb[1],                    fmb = mkb[2];
    float2 bea = emb2[(size_t)(LL - 1) * 32], beb = emb2[(size_t)(LL - 2) * 32];
    float  bma = mkb[LL - 1],                bmb = mkb[LL - 2];

    int cur = 0;
#define ADV(fti, bti)                                                     \
    {                                                                     \
        int a_ = (fti); if (a_ > LL - 1) a_ = LL - 1;                     \
        int c_ = (bti); if (c_ < 0) c_ = 0;                               \
        fea = feb; fma_ = fmb; feb = emb2[(size_t)a_ * 32]; fmb = mkb[a_];\
        bea = beb; bma = bmb; beb = emb2[(size_t)c_ * 32]; bmb = mkb[c_];\
    }

#define SS(MODE, fti, bti)                                                \
    {                                                                     \
        float2 ef_ = fea; float mf_ = fma_;                               \
        float2 eg_ = bea; float mg_ = bma;                                \
        ADV(fti, bti);                                                    \
        sstep<MODE>(ef_, mf_, eg_, mg_, vf0, vf1, Sf, mxF,                \
                    w0, w1, Sb, mxB, cur, vF, vB, eFA, eFB, eBA, eBB, lane);\
    }

    // main: 255 quads = 1020 supersteps; fwd steps 1..1020, bwd idx 2047..1028
#pragma unroll 1
    for (int i = 0; i < 255; ++i) {
        int tf = 1 + 4 * i;          // fwd steps tf..tf+3
        int bi = (LL - 1) - 4 * i;   // bwd emission indices bi..bi-3
        SS(1, tf + 2, bi - 2);
        SS(2, tf + 3, bi - 3);
        SS(0, tf + 4, bi - 4);
        SS(0, tf + 5, bi - 5);
    }
    // tail: 3 joint supersteps (fwd 1021..1023; bwd idx 1027..1025)
    SS(0, 1023, 1025);
    SS(0, 1023, 1024);
    SS(0, 1023, 1024);
    // final bwd-only step (emission idx 1024) -> w at position MID
    {
        float eg0 = __expf(bea.x), eg1 = __expf(bea.y);
        int nxt = cur ^ 1;
        vB[nxt][lane] = bfpack(w0 * eg0, w1 * eg1);
        __syncwarp();
        float ab0, ab1;
        dot2(vB[nxt], eBA, eBB, ab0, ab1);
        if (bma > 0.f) { w0 = ab0; w1 = ab1; }
    }
#undef SS
#undef ADV

    // logZ = log( sum_c alpha_MID[c] * w_MID[c] ) + S_f + S_b  (all in-warp)
    float term = vf0 * w0 + vf1 * w1;
#pragma unroll
    for (int o = 16; o; o >>= 1) term += __shfl_xor_sync(0xffffffffu, term, o);
    if (lane == 0) g_part[b] = __logf(term) + Sf + Sb;
}

// ---------------------------------------------------------------------------
// Gold path score per batch (cheap gathers) — exact fp32.
// ---------------------------------------------------------------------------
__global__ void __launch_bounds__(256) scores_kernel(const float* __restrict__ em,
                                                     const float* __restrict__ T,
                                                     const float* __restrict__ mask,
                                                     const int* __restrict__ tags) {
    const int b   = blockIdx.x;
    const int tid = threadIdx.x;
    const float* emb = em + (size_t)b * (LL * CC);
    const float* mkb = mask + (size_t)b * LL;
    const int*   tgb = tags + (size_t)b * LL;

    float acc = 0.f, msum = 0.f;
    for (int t = tid; t < LL; t += 256) {
        msum += mkb[t];
        if (t >= 1) {
            int tg = tgb[t];
            int tq = tgb[t - 1];
            acc += (emb[(size_t)t * CC + tg] + T[tq * CC + tg]) * mkb[t];
        }
    }

    __shared__ float sacc[8], smsum[8];
#pragma unroll
    for (int o = 16; o; o >>= 1) {
        acc  += __shfl_xor_sync(0xffffffffu, acc, o);
        msum += __shfl_xor_sync(0xffffffffu, msum, o);
    }
    int lane = tid & 31, w = tid >> 5;
    if (lane == 0) { sacc[w] = acc; smsum[w] = msum; }
    __syncthreads();
    if (tid == 0) {
        float A = 0.f, M = 0.f;
#pragma unroll
        for (int i = 0; i < 8; ++i) { A += sacc[i]; M += smsum[i]; }
        int t0 = tgb[0];
        float s = A + emb[t0] + T[START_S * CC + t0];
        int last = (int)M - 1;               // mask sum of 1.0s is exact in fp32
        s += T[tgb[last] * CC + STOP_S];
        g_scores[b] = s;
    }
}

// ---------------------------------------------------------------------------
// mean(partition - scores)
// ---------------------------------------------------------------------------
__global__ void __launch_bounds__(512) finalize_kernel(float* __restrict__ out) {
    int tid = threadIdx.x;
    float d = g_part[tid] - g_scores[tid];
    __shared__ float sh[16];
#pragma unroll
    for (int o = 16; o; o >>= 1) d += __shfl_xor_sync(0xffffffffu, d, o);
    if ((tid & 31) == 0) sh[tid >> 5] = d;
    __syncthreads();
    if (tid < 16) {
        float x = sh[tid];
#pragma unroll
        for (int o = 8; o; o >>= 1) x += __shfl_xor_sync(0x0000ffffu, x, o);
        if (tid == 0) out[0] = x * (1.0f / BB);
    }
}

extern "C" void kernel_launch(void* const* d_in, const int* in_sizes, int n_in,
                              void* d_out, int out_size) {
    (void)in_sizes; (void)n_in; (void)out_size;
    const float* em   = (const float*)d_in[0];
    const float* T    = (const float*)d_in[1];
    const float* mask = (const float*)d_in[2];
    const int*   tags = (const int*)d_in[3];
    float* out = (float*)d_out;

    prep_kernel<<<4, 512>>>(T);
    alpha_kernel<<<BB / 4, 128>>>(em, mask);
    scores_kernel<<<BB, 256>>>(em, T, mask, tags);
    finalize_kernel<<<1, 512>>>(out);
}

// round 12
// speedup vs baseline: 1.4615x; 1.4615x over previous
#include <cuda_runtime.h>
#include <cuda_bf16.h>

#define BB 512
#define LL 2048
#define CC 64
#define START_S 62
#define STOP_S 63
#define MID 1023

// scratch (no cudaMalloc allowed)
__device__ unsigned g_eTbfF[CC * 32]; // fwd:  [cp][k2] = bf16x2{exp(T[2k2][cp]), exp(T[2k2+1][cp])}
__device__ unsigned g_eTbfB[CC * 32]; // bwd:  [c][k2]  = bf16x2{exp(T[c][2k2]),  exp(T[c][2k2+1])}
__device__ float g_eTstop[CC];        // exp(T[c][STOP])
__device__ float g_trow_start[CC];    // T[START][c]
__device__ float g_part[BB];
__device__ float g_scores[BB];

// bf16x2 packed ops
__device__ __forceinline__ unsigned bffma(unsigned a, unsigned b, unsigned c) {
    unsigned d;
    asm("fma.rn.bf16x2 %0, %1, %2, %3;" : "=r"(d) : "r"(a), "r"(b), "r"(c));
    return d;
}
__device__ __forceinline__ unsigned bfadd(unsigned a, unsigned b) {
    unsigned d;
    asm("add.rn.bf16x2 %0, %1, %2;" : "=r"(d) : "r"(a), "r"(b));
    return d;
}
__device__ __forceinline__ float bfsum(unsigned ab) {
    float lo = __uint_as_float(ab << 16);
    float hi = __uint_as_float(ab & 0xffff0000u);
    return lo + hi;
}
__device__ __forceinline__ unsigned bfpack(float x, float y) {
    unsigned d;
    asm("cvt.rn.bf16x2.f32 %0, %1, %2;" : "=r"(d) : "f"(y), "f"(x));
    return d;
}

// ---------------------------------------------------------------------------
// Precompute both packed exp(T) tables + boundary vectors.
// ---------------------------------------------------------------------------
__global__ void prep_kernel(const float* __restrict__ T) {
    int i = blockIdx.x * blockDim.x + threadIdx.x;
    if (i < CC * 32) {
        int c  = i >> 5;
        int k2 = i & 31;
        __nv_bfloat162 pf = __floats2bfloat162_rn(__expf(T[(2 * k2) * CC + c]),
                                                  __expf(T[(2 * k2 + 1) * CC + c]));
        g_eTbfF[i] = *reinterpret_cast<unsigned*>(&pf);
        __nv_bfloat162 pb = __floats2bfloat162_rn(__expf(T[c * CC + 2 * k2]),
                                                  __expf(T[c * CC + 2 * k2 + 1]));
        g_eTbfB[i] = *reinterpret_cast<unsigned*>(&pb);
    }
    if (i < CC) {
        g_eTstop[i]     = __expf(T[i * CC + STOP_S]);
        g_trow_start[i] = T[START_S * CC + i];
    }
}

// two interleaved 64-dots in bf16x2 (this lane's two output states)
__device__ __forceinline__ void dot2(const unsigned* __restrict__ vsh32,
                                     const unsigned* __restrict__ eA,
                                     const unsigned* __restrict__ eB,
                                     float& ra, float& rb) {
    const uint4* q = reinterpret_cast<const uint4*>(vsh32);
    unsigned a0 = 0, a1 = 0, a2 = 0, a3 = 0;
    unsigned b0 = 0, b1 = 0, b2 = 0, b3 = 0;
#pragma unroll
    for (int j = 0; j < 8; ++j) {
        uint4 x = q[j];
        a0 = bffma(x.x, eA[4 * j + 0], a0);
        b0 = bffma(x.x, eB[4 * j + 0], b0);
        a1 = bffma(x.y, eA[4 * j + 1], a1);
        b1 = bffma(x.y, eB[4 * j + 1], b1);
        a2 = bffma(x.z, eA[4 * j + 2], a2);
        b2 = bffma(x.z, eB[4 * j + 2], b2);
        a3 = bffma(x.w, eA[4 * j + 3], a3);
        b3 = bffma(x.w, eB[4 * j + 3], b3);
    }
    ra = bfsum(bfadd(bfadd(a0, a1), bfadd(a2, a3)));
    rb = bfsum(bfadd(bfadd(b0, b1), bfadd(b2, b3)));
}

// forward step: v' = (e_t ⊙ (expT^T v)) ; MODE: 0 plain, 1 launch max, 2 renorm
template <int MODE>
__device__ __forceinline__ void stepF(float2 ev, float mkv,
                                      float& v0, float& v1, float& S, float& mx,
                                      int& cur, unsigned (*vsh)[32],
                                      const unsigned* __restrict__ eA,
                                      const unsigned* __restrict__ eB,
                                      int lane) {
    if (MODE == 1) {
        float x = fmaxf(v0, v1);
#pragma unroll
        for (int o = 16; o; o >>= 1) x = fmaxf(x, __shfl_xor_sync(0xffffffffu, x, o));
        mx = x;
    }
    float ee0 = __expf(ev.x);
    float ee1 = __expf(ev.y);
    float vr0 = v0, vr1 = v1;
    if (MODE == 2) {
        float r = __fdividef(1.0f, mx);
        S += __logf(mx);
        ee0 *= r; vr0 = v0 * r;
        ee1 *= r; vr1 = v1 * r;
    }
    float a, bq;
    dot2(vsh[cur], eA, eB, a, bq);
    float nv0 = (mkv > 0.f) ? a  * ee0 : vr0;
    float nv1 = (mkv > 0.f) ? bq * ee1 : vr1;
    v0 = nv0; v1 = nv1;
    vsh[cur ^ 1][lane] = bfpack(nv0, nv1);
    __syncwarp();
    cur ^= 1;
}

// backward step: w' = expT (e_{t+1} ⊙ w) ; emission applied BEFORE the dot
template <int MODE>
__device__ __forceinline__ void stepB(float2 ev, float mkv,
                                      float& v0, float& v1, float& S, float& mx,
                                      int& cur, unsigned (*vsh)[32],
                                      const unsigned* __restrict__ eA,
                                      const unsigned* __restrict__ eB,
                                      int lane) {
    if (MODE == 1) {
        float x = fmaxf(v0, v1);
#pragma unroll
        for (int o = 16; o; o >>= 1) x = fmaxf(x, __shfl_xor_sync(0xffffffffu, x, o));
        mx = x;
    }
    float ee0 = __expf(ev.x);
    float ee1 = __expf(ev.y);
    float vr0 = v0, vr1 = v1;
    if (MODE == 2) {
        float r = __fdividef(1.0f, mx);
        S += __logf(mx);
        ee0 *= r; vr0 = v0 * r;
        ee1 *= r; vr1 = v1 * r;
    }
    int nxt = cur ^ 1;
    vsh[nxt][lane] = bfpack(v0 * ee0, v1 * ee1);   // u = e⊙w (renorm folded in ee)
    __syncwarp();
    float a, bq;
    dot2(vsh[nxt], eA, eB, a, bq);
    v0 = (mkv > 0.f) ? a  : vr0;
    v1 = (mkv > 0.f) ? bq : vr1;
    cur = nxt;
}

// ---------------------------------------------------------------------------
// Bidirectional forward algorithm in exp-space, bf16 matvec.
// 256 CTAs x 128 threads = TWO batches per CTA, 4 warps covering all 4 SMSPs
// (fwd_b0, bwd_b0, fwd_b1, bwd_b1) — fixes R10's half-idle-scheduler layout.
// Per warp identical to R10: lane owns 2 states, exp(T) in 64 bf16x2 regs,
// v exchanged via a private 128B bf16x2 buffer with __syncwarp only; fwd runs
// steps 1..MID, bwd runs the transposed recursion from L-1 down to MID+1;
//   logZ = log( sum_c alpha_MID[c] * w_MID[c] ) + S_f + S_b.
// Renorm every 4 steps, max-shuffle pipelined off the chain.
// ---------------------------------------------------------------------------
__global__ void __launch_bounds__(128, 1) alpha_kernel(const float* __restrict__ em,
                                                       const float* __restrict__ mask) {
    const int lane = threadIdx.x & 31;
    const int wid  = threadIdx.x >> 5;
    const int pair = wid >> 1;           // batch slot in CTA (0 or 1)
    const int dir  = wid & 1;            // 0 = forward, 1 = backward
    const int b    = blockIdx.x * 2 + pair;

    __shared__ __align__(16) unsigned vshbuf[4][2][32];  // [warp][buf][lane]
    __shared__ float warr[2][CC];
    __shared__ float sSb[2];

    const float* emb = em + (size_t)b * (LL * CC);
    const float* mkb = mask + (size_t)b * LL;
    const float2* emb2 = reinterpret_cast<const float2*>(emb) + lane;

    unsigned (*vsh)[32] = vshbuf[wid];

    float v0, v1, S = 0.0f, mx = 0.0f;

    if (dir == 0) {
        // ---------------- forward half: steps 1..MID ----------------
        unsigned eA[32], eB[32];
        {
            const unsigned* ga = g_eTbfF + (2 * lane) * 32;
            const unsigned* gb = g_eTbfF + (2 * lane + 1) * 32;
#pragma unroll
            for (int k = 0; k < 32; ++k) { eA[k] = ga[k]; eB[k] = gb[k]; }
        }
        v0 = __expf(emb2[0].x + g_trow_start[2 * lane]);
        v1 = __expf(emb2[0].y + g_trow_start[2 * lane + 1]);
        vsh[0][lane] = bfpack(v0, v1);

        float2 ea = emb2[1 * 32], eb = emb2[2 * 32], ec = emb2[3 * 32];
        float  ma = mkb[1],       mb = mkb[2],       mc = mkb[3];
        __syncwarp();

        int cur = 0;
#define ADVF(t_)                                                        \
        {                                                               \
            int ti = (t_) + 3; if (ti > MID) ti = MID;                  \
            float2 en = emb2[(size_t)ti * 32];                          \
            float  mn = mkb[ti];                                        \
            ea = eb; ma = mb; eb = ec; mb = mc; ec = en; mc = mn;       \
        }
#pragma unroll 1
        for (int t = 1; t <= MID - 3; t += 4) {
            float2 e0 = ea; float m0 = ma; ADVF(t);
            stepF<1>(e0, m0, v0, v1, S, mx, cur, vsh, eA, eB, lane);
            e0 = ea; m0 = ma; ADVF(t + 1);
            stepF<2>(e0, m0, v0, v1, S, mx, cur, vsh, eA, eB, lane);
            e0 = ea; m0 = ma; ADVF(t + 2);
            stepF<0>(e0, m0, v0, v1, S, mx, cur, vsh, eA, eB, lane);
            e0 = ea; m0 = ma; ADVF(t + 3);
            stepF<0>(e0, m0, v0, v1, S, mx, cur, vsh, eA, eB, lane);
        }
        // tail: steps MID-2, MID-1, MID  (1020 done above)
#pragma unroll 1
        for (int t = MID - 2; t <= MID; ++t) {
            float2 e0 = ea; float m0 = ma; ADVF(t);
            stepF<0>(e0, m0, v0, v1, S, mx, cur, vsh, eA, eB, lane);
        }
#undef ADVF
    } else {
        // ---------------- backward half: steps L-2 .. MID ----------------
        unsigned eA[32], eB[32];
        {
            const unsigned* ga = g_eTbfB + (2 * lane) * 32;
            const unsigned* gb = g_eTbfB + (2 * lane + 1) * 32;
#pragma unroll
            for (int k = 0; k < 32; ++k) { eA[k] = ga[k]; eB[k] = gb[k]; }
        }
        v0 = g_eTstop[2 * lane];
        v1 = g_eTstop[2 * lane + 1];

        float2 ea = emb2[(size_t)(LL - 1) * 32];
        float2 eb = emb2[(size_t)(LL - 2) * 32];
        float2 ec = emb2[(size_t)(LL - 3) * 32];
        float  ma = mkb[LL - 1], mb = mkb[LL - 2], mc = mkb[LL - 3];
        __syncwarp();

        int cur = 0;
#define ADVB(t_)                                                        \
        {                                                               \
            int ti = (t_) - 2; if (ti < 0) ti = 0;                      \
            float2 en = emb2[(size_t)ti * 32];                          \
            float  mn = mkb[ti];                                        \
            ea = eb; ma = mb; eb = ec; mb = mc; ec = en; mc = mn;       \
        }
        // 1024 steps: t = LL-2 down to MID, exactly 256 quads
#pragma unroll 1
        for (int t = LL - 2; t > MID; t -= 4) {
            float2 e0 = ea; float m0 = ma; ADVB(t);
            stepB<1>(e0, m0, v0, v1, S, mx, cur, vsh, eA, eB, lane);
            e0 = ea; m0 = ma; ADVB(t - 1);
            stepB<2>(e0, m0, v0, v1, S, mx, cur, vsh, eA, eB, lane);
            e0 = ea; m0 = ma; ADVB(t - 2);
            stepB<0>(e0, m0, v0, v1, S, mx, cur, vsh, eA, eB, lane);
            e0 = ea; m0 = ma; ADVB(t - 3);
            stepB<0>(e0, m0, v0, v1, S, mx, cur, vsh, eA, eB, lane);
        }
#undef ADVB
        warr[pair][2 * lane]     = v0;
        warr[pair][2 * lane + 1] = v1;
        if (lane == 0) sSb[pair] = S;
    }

    __syncthreads();

    if (dir == 0) {
        // logZ = log( sum_c valpha[c] * w[c] ) + S_f + S_b
        float term = v0 * warr[pair][2 * lane] + v1 * warr[pair][2 * lane + 1];
#pragma unroll
        for (int o = 16; o; o >>= 1) term += __shfl_xor_sync(0xffffffffu, term, o);
        if (lane == 0) g_part[b] = __logf(term) + S + sSb[pair];
    }
}

// ---------------------------------------------------------------------------
// Gold path score per batch (cheap gathers) — exact fp32.
// ---------------------------------------------------------------------------
__global__ void __launch_bounds__(256) scores_kernel(const float* __restrict__ em,
                                                     const float* __restrict__ T,
                                                     const float* __restrict__ mask,
                                                     const int* __restrict__ tags) {
    const int b   = blockIdx.x;
    const int tid = threadIdx.x;
    const float* emb = em + (size_t)b * (LL * CC);
    const float* mkb = mask + (size_t)b * LL;
    const int*   tgb = tags + (size_t)b * LL;

    float acc = 0.f, msum = 0.f;
    for (int t = tid; t < LL; t += 256) {
        msum += mkb[t];
        if (t >= 1) {
            int tg = tgb[t];
            int tq = tgb[t - 1];
            acc += (emb[(size_t)t * CC + tg] + T[tq * CC + tg]) * mkb[t];
        }
    }

    __shared__ float sacc[8], smsum[8];
#pragma unroll
    for (int o = 16; o; o >>= 1) {
        acc  += __shfl_xor_sync(0xffffffffu, acc, o);
        msum += __shfl_xor_sync(0xffffffffu, msum, o);
    }
    int lane = tid & 31, w = tid >> 5;
    if (lane == 0) { sacc[w] = acc; smsum[w] = msum; }
    __syncthreads();
    if (tid == 0) {
        float A = 0.f, M = 0.f;
#pragma unroll
        for (int i = 0; i < 8; ++i) { A += sacc[i]; M += smsum[i]; }
        int t0 = tgb[0];
        float s = A + emb[t0] + T[START_S * CC + t0];
        int last = (int)M - 1;               // mask sum of 1.0s is exact in fp32
        s += T[tgb[last] * CC + STOP_S];
        g_scores[b] = s;
    }
}

// ---------------------------------------------------------------------------
// mean(partition - scores)
// ---------------------------------------------------------------------------
__global__ void __launch_bounds__(512) finalize_kernel(float* __restrict__ out) {
    int tid = threadIdx.x;
    float d = g_part[tid] - g_scores[tid];
    __shared__ float sh[16];
#pragma unroll
    for (int o = 16; o; o >>= 1) d += __shfl_xor_sync(0xffffffffu, d, o);
    if ((tid & 31) == 0) sh[tid >> 5] = d;
    __syncthreads();
    if (tid < 16) {
        float x = sh[tid];
#pragma unroll
        for (int o = 8; o; o >>= 1) x += __shfl_xor_sync(0x0000ffffu, x, o);
        if (tid == 0) out[0] = x * (1.0f / BB);
    }
}

extern "C" void kernel_launch(void* const* d_in, const int* in_sizes, int n_in,
                              void* d_out, int out_size) {
    (void)in_sizes; (void)n_in; (void)out_size;
    const float* em   = (const float*)d_in[0];
    const float* T    = (const float*)d_in[1];
    const float* mask = (const float*)d_in[2];
    const int*   tags = (const int*)d_in[3];
    float* out = (float*)d_out;

    prep_kernel<<<4, 512>>>(T);
    alpha_kernel<<<BB / 2, 128>>>(em, mask);
    scores_kernel<<<BB, 256>>>(em, T, mask, tags);
    finalize_kernel<<<1, 512>>>(out);
}